// round 9
// baseline (speedup 1.0000x reference)
#include <cuda_runtime.h>
#include <cuda_fp16.h>

// ODECell: f = sigmoid(sigma*(in-mu)) = 0.5 + 0.5*tanh(0.5*sigma*(in-mu))
//   t = tanh(sH*x + cH);  fA = baseA[u] + sum_d t*AH;  fs = 64 + 0.5*sum_d t
//   x <- 6 Euler steps of x*(1 - dt*(omega+fs)) + dt*fA
//
// R9: intra-block d-split. 256 threads = (u, d-half); each half reduces 16
// quads for the same 2 batches; combine via 4KB smem. Grid stays 1024 but
// warps/SM double (86% occ cap). f16x2 tanh + grouped f16 accumulation.

#define UNITS 128
#define IDIM  128
#define DP    (IDIM / 2)     // 64 d-pairs
#define NQ    (DP / 2)       // 32 d-quads (4 dims each)
#define NQH   (NQ / 2)       // 16 quads per thread-half
#define GQ    4              // quads per flush group (16 dims)
#define NGH   (NQH / GQ)     // 4 groups per half
#define BATCH 2048
#define BB    2
#define OMEGA 0.1f
#define DT_U  (0.1f / 6.0f)

typedef unsigned int       u32;
typedef unsigned long long u64;

// Weight streams, transposed [quad][u]:
//   g_wsc: {sH2_a, cH2_a, sH2_b, cH2_b}  (uint4, 16B per 4 dims)
//   g_wa : {AH2_a, AH2_b}                (uint2,  8B per 4 dims)
__device__ uint4 g_wsc[NQ * UNITS];
__device__ uint2 g_wa [NQ * UNITS];
__device__ float g_baseA[UNITS];

__device__ __forceinline__ u32 h2u(__half2 h) {
    u32 r; __builtin_memcpy(&r, &h, 4); return r;
}
__device__ __forceinline__ __half2 u2h(u32 u) {
    __half2 r; __builtin_memcpy(&r, &u, 4); return r;
}
__device__ __forceinline__ u32 tanh2u(u32 z) {
    u32 y; asm("tanh.approx.f16x2 %0, %1;" : "=r"(y) : "r"(z)); return y;
}
__device__ __forceinline__ u32 hfma2u(u32 a, u32 b, u32 c) {
    return h2u(__hfma2(u2h(a), u2h(b), u2h(c)));
}
__device__ __forceinline__ u32 hadd2u(u32 a, u32 b) {
    return h2u(__hadd2(u2h(a), u2h(b)));
}
__device__ __forceinline__ u64 pack2(float lo, float hi) {
    u64 p;
    asm("mov.b64 %0, {%1, %2};" : "=l"(p)
        : "r"(__float_as_uint(lo)), "r"(__float_as_uint(hi)));
    return p;
}
__device__ __forceinline__ u64 add2(u64 a, u64 b) {
    u64 d; asm("add.rn.f32x2 %0, %1, %2;" : "=l"(d) : "l"(a), "l"(b));
    return d;
}
__device__ __forceinline__ float2 unpack2(u64 p) {
    u32 lo, hi;
    asm("mov.b64 {%0, %1}, %2;" : "=r"(lo), "=r"(hi) : "l"(p));
    return make_float2(__uint_as_float(lo), __uint_as_float(hi));
}
__device__ __forceinline__ u64 cvt2(u32 h) {   // f16x2 -> packed f32x2
    __half2 hh = u2h(h);
    return pack2(__low2float(hh), __high2float(hh));
}

// One block per unit u, 64 threads (one per d-pair): pack weights + reduce baseA.
__global__ void ode_prep_kernel(const float* __restrict__ A,
                                const float* __restrict__ sigma,
                                const float* __restrict__ mu) {
    const int u   = blockIdx.x;
    const int d2  = threadIdx.x;          // 0..63
    const int i   = u * IDIM + 2 * d2;
    const int q   = d2 >> 1;              // quad index
    const int sub = d2 & 1;               // a/b within quad

    float s0 = sigma[i],  s1 = sigma[i + 1];
    float m0 = mu[i],     m1 = mu[i + 1];
    float a0 = 0.5f * A[i], a1 = 0.5f * A[i + 1];

    u32 sh2 = h2u(__halves2half2(__float2half_rn(0.5f * s0), __float2half_rn(0.5f * s1)));
    u32 ch2 = h2u(__halves2half2(__float2half_rn(-0.5f * s0 * m0),
                                 __float2half_rn(-0.5f * s1 * m1)));
    u32 ah2 = h2u(__halves2half2(__float2half_rn(a0), __float2half_rn(a1)));

    u32* wsc = (u32*)&g_wsc[q * UNITS + u];
    wsc[sub * 2 + 0] = sh2;
    wsc[sub * 2 + 1] = ch2;
    u32* wa = (u32*)&g_wa[q * UNITS + u];
    wa[sub] = ah2;

    __shared__ float red[2];
    float v = a0 + a1;
    #pragma unroll
    for (int off = 16; off > 0; off >>= 1)
        v += __shfl_down_sync(0xffffffffu, v, off);
    if ((d2 & 31) == 0) red[d2 >> 5] = v;
    __syncthreads();
    if (d2 == 0) g_baseA[u] = red[0] + red[1];
}

__global__ __launch_bounds__(256, 7)   // 36-reg cap; 7 blocks/SM covers grid 1024 in 1 wave
void ode_main_kernel(const float* __restrict__ inputs,
                     const float* __restrict__ state,
                     float* __restrict__ out) {
    const int tid = threadIdx.x;
    const int u   = tid & (UNITS - 1);
    const int h   = tid >> 7;            // d-half 0/1
    const int b0  = blockIdx.x * BB;

    __shared__ u32    s_x[DP * 2];       // half2 x-pairs, both batches
    __shared__ float4 s_part[256];       // (fA0, st0, fA1, st1) partials

    if (tid < DP) {
        const float2* in2 = (const float2*)inputs;
        float2 xa = in2[(b0 * IDIM) / 2 + tid];
        float2 xb = in2[((b0 + 1) * IDIM) / 2 + tid];
        s_x[2 * tid + 0] = h2u(__halves2half2(__float2half_rn(xa.x), __float2half_rn(xa.y)));
        s_x[2 * tid + 1] = h2u(__halves2half2(__float2half_rn(xb.x), __float2half_rn(xb.y)));
    }
    __syncthreads();
    const uint4* s_x4 = (const uint4*)s_x;   // [q] -> {xb0_a, xb1_a, xb0_b, xb1_b}

    u64 acc0 = 0, st0 = 0;   // packed f32x2 totals per batch (this d-half)
    u64 acc1 = 0, st1 = 0;

    const int qbase = h * NQH;
    const uint4* __restrict__ wsc = &g_wsc[qbase * UNITS + u];
    const uint2* __restrict__ wa  = &g_wa [qbase * UNITS + u];

    #pragma unroll
    for (int g = 0; g < NGH; ++g) {
        u32 accg0 = 0, stg0 = 0;   // f16x2 group accumulators
        u32 accg1 = 0, stg1 = 0;

        #pragma unroll
        for (int j = 0; j < GQ; ++j) {
            const int q = g * GQ + j;
            uint4 wv = __ldg(&wsc[q * UNITS]);   // LDG.128
            uint2 av = __ldg(&wa [q * UNITS]);   // LDG.64
            uint4 xp = s_x4[qbase + q];          // LDS.128 broadcast

            // subpair a (dims 4q, 4q+1)
            u32 ta0 = tanh2u(hfma2u(wv.x, xp.x, wv.y));
            u32 ta1 = tanh2u(hfma2u(wv.x, xp.y, wv.y));
            accg0 = hfma2u(ta0, av.x, accg0);  stg0 = hadd2u(stg0, ta0);
            accg1 = hfma2u(ta1, av.x, accg1);  stg1 = hadd2u(stg1, ta1);

            // subpair b (dims 4q+2, 4q+3)
            u32 tb0 = tanh2u(hfma2u(wv.z, xp.z, wv.w));
            u32 tb1 = tanh2u(hfma2u(wv.z, xp.w, wv.w));
            accg0 = hfma2u(tb0, av.y, accg0);  stg0 = hadd2u(stg0, tb0);
            accg1 = hfma2u(tb1, av.y, accg1);  stg1 = hadd2u(stg1, tb1);
        }

        acc0 = add2(acc0, cvt2(accg0));  st0 = add2(st0, cvt2(stg0));
        acc1 = add2(acc1, cvt2(accg1));  st1 = add2(st1, cvt2(stg1));
    }

    {
        float2 a0 = unpack2(acc0), s0 = unpack2(st0);
        float2 a1 = unpack2(acc1), s1 = unpack2(st1);
        s_part[tid] = make_float4(a0.x + a0.y, s0.x + s0.y,
                                  a1.x + a1.y, s1.x + s1.y);
    }
    __syncthreads();

    if (tid < UNITS) {
        float4 p0 = s_part[tid];
        float4 p1 = s_part[tid + UNITS];
        const float baseA = g_baseA[u];

        {
            float fA = baseA + p0.x + p1.x;
            float fs = (float)(IDIM / 2) + 0.5f * (p0.y + p1.y);
            float am = 1.0f - DT_U * (OMEGA + fs);
            float c  = DT_U * fA;
            float x  = state[b0 * UNITS + u];
            #pragma unroll
            for (int k = 0; k < 6; ++k) x = fmaf(x, am, c);
            out[b0 * UNITS + u] = x;
        }
        {
            float fA = baseA + p0.z + p1.z;
            float fs = (float)(IDIM / 2) + 0.5f * (p0.w + p1.w);
            float am = 1.0f - DT_U * (OMEGA + fs);
            float c  = DT_U * fA;
            float x  = state[(b0 + 1) * UNITS + u];
            #pragma unroll
            for (int k = 0; k < 6; ++k) x = fmaf(x, am, c);
            out[(b0 + 1) * UNITS + u] = x;
        }
    }
}

extern "C" void kernel_launch(void* const* d_in, const int* in_sizes, int n_in,
                              void* d_out, int out_size) {
    const float* inputs = (const float*)d_in[0];
    const float* state  = (const float*)d_in[1];
    const float* A      = (const float*)d_in[2];
    const float* sigma  = (const float*)d_in[3];
    const float* mu     = (const float*)d_in[4];
    float* out = (float*)d_out;

    ode_prep_kernel<<<UNITS, DP>>>(A, sigma, mu);
    ode_main_kernel<<<BATCH / BB, 256>>>(inputs, state, out);
}